// round 1
// baseline (speedup 1.0000x reference)
#include <cuda_runtime.h>
#include <cuda_bf16.h>

// Performer (FAVOR+) linear attention, fp32 SIMT baseline.
// B=4 H=16 S=4096 D=64 M=64. Inputs: query, key, value, omega. Output fp32 (B,H,S,D).

#define Sc 4096
#define Dc 64
#define Mc 64
#define Ec 65        // D + 1 (value concat ones)
#define EP 68        // padded C row stride in smem
#define BH 64        // B*H
#define CHUNK 128
#define NCHUNK (Sc / CHUNK)
#define RSQRT_M 0.125f   // 1/sqrt(64)

// Scratch for buf1 = kp^T @ [V, 1]  per (b,h): [BH][M][E]
__device__ float g_buf1[BH * Mc * Ec];

__global__ void zero_buf1() {
    int i = blockIdx.x * blockDim.x + threadIdx.x;
    if (i < BH * Mc * Ec) g_buf1[i] = 0.0f;
}

// ---------------------------------------------------------------------------
// Phase 1: kp features + partial outer-product accumulation into g_buf1.
// grid = (NCHUNK, BH), 256 threads.
// smem: omega[64][64] | kp[CHUNK][64] | C[CHUNK][EP]
// ---------------------------------------------------------------------------
__global__ __launch_bounds__(256) void phase1(const float* __restrict__ K,
                                              const float* __restrict__ V,
                                              const float* __restrict__ W) {
    extern __shared__ float sm[];
    float* ws  = sm;                 // 64*64
    float* kps = ws + 64 * 64;       // CHUNK*64
    float* cs  = kps + CHUNK * 64;   // CHUNK*EP

    const int bh = blockIdx.y;
    const int chunk = blockIdx.x;

    // load omega (D-major: ws[d*64 + m])
    {
        const float4* W4 = (const float4*)W;
        float4* S4 = (float4*)ws;
        for (int i = threadIdx.x; i < 64 * 64 / 4; i += blockDim.x) S4[i] = W4[i];
    }
    __syncthreads();

    const int warp = threadIdx.x >> 5;
    const int lane = threadIdx.x & 31;
    const size_t base = ((size_t)bh * Sc + (size_t)chunk * CHUNK) * Dc;
    const float* Kc = K + base;
    const float* Vc = V + base;

    for (int r = warp; r < CHUNK; r += 8) {
        float k0 = Kc[r * Dc + lane];
        float k1 = Kc[r * Dc + lane + 32];
        float v0 = Vc[r * Dc + lane];
        float v1 = Vc[r * Dc + lane + 32];
        cs[r * EP + lane]      = v0;
        cs[r * EP + lane + 32] = v1;
        if (lane == 0) cs[r * EP + 64] = 1.0f;

        float ksq = fmaf(k0, k0, k1 * k1);
        #pragma unroll
        for (int o = 16; o > 0; o >>= 1) ksq += __shfl_xor_sync(0xffffffffu, ksq, o);

        float u0 = 0.f, u1 = 0.f;
        #pragma unroll
        for (int d = 0; d < 32; d++) {
            float kd = __shfl_sync(0xffffffffu, k0, d);
            u0 = fmaf(kd, ws[d * 64 + lane], u0);
            u1 = fmaf(kd, ws[d * 64 + lane + 32], u1);
        }
        #pragma unroll
        for (int d = 0; d < 32; d++) {
            float kd = __shfl_sync(0xffffffffu, k1, d);
            u0 = fmaf(kd, ws[(d + 32) * 64 + lane], u0);
            u1 = fmaf(kd, ws[(d + 32) * 64 + lane + 32], u1);
        }
        const float c = -0.5f * ksq;
        kps[r * 64 + lane]      = __expf(u0 + c) * RSQRT_M;
        kps[r * 64 + lane + 32] = __expf(u1 + c) * RSQRT_M;
    }
    __syncthreads();

    // Outer product: buf1[m][e] += sum_r kp[r][m] * C[r][e]
    // thread -> (m = tid&63, eg = tid>>6); e = eg + 4*j
    const int m  = threadIdx.x & 63;
    const int eg = threadIdx.x >> 6;   // 0..3 (uniform per warp -> C reads broadcast)
    float acc[17];
    #pragma unroll
    for (int j = 0; j < 17; j++) acc[j] = 0.f;

    for (int r = 0; r < CHUNK; r++) {
        float kv = kps[r * 64 + m];
        #pragma unroll
        for (int j = 0; j < 17; j++) {
            int e = eg + 4 * j;
            if (e < Ec) acc[j] = fmaf(kv, cs[r * EP + e], acc[j]);
        }
    }

    float* b1 = g_buf1 + (bh * Mc + m) * Ec;
    #pragma unroll
    for (int j = 0; j < 17; j++) {
        int e = eg + 4 * j;
        if (e < Ec) atomicAdd(&b1[e], acc[j]);
    }
}

// ---------------------------------------------------------------------------
// Phase 2: qp features, out = (qp @ buf1[:, :64]) / (qp @ buf1[:, 64])
// grid = (NCHUNK, BH), 256 threads.
// smem: omega[64][64] | buf1[64][66]
// ---------------------------------------------------------------------------
__global__ __launch_bounds__(256) void phase2(const float* __restrict__ Q,
                                              const float* __restrict__ W,
                                              float* __restrict__ O) {
    extern __shared__ float sm[];
    float* ws  = sm;             // 64*64
    float* b1s = ws + 64 * 64;   // 64*66 (padded)

    const int bh = blockIdx.y;
    const int chunk = blockIdx.x;

    {
        const float4* W4 = (const float4*)W;
        float4* S4 = (float4*)ws;
        for (int i = threadIdx.x; i < 64 * 64 / 4; i += blockDim.x) S4[i] = W4[i];
    }
    {
        const float* b1 = g_buf1 + bh * Mc * Ec;
        for (int i = threadIdx.x; i < Mc * Ec; i += blockDim.x) {
            int mm = i / Ec, ee = i - mm * Ec;
            b1s[mm * 66 + ee] = b1[i];
        }
    }
    __syncthreads();

    const int warp = threadIdx.x >> 5;
    const int lane = threadIdx.x & 31;
    const size_t base = ((size_t)bh * Sc + (size_t)chunk * CHUNK) * Dc;
    const float* Qc = Q + base;
    float* Oc = O + base;

    for (int r = warp; r < CHUNK; r += 8) {
        float q0 = Qc[r * Dc + lane];
        float q1 = Qc[r * Dc + lane + 32];

        float qsq = fmaf(q0, q0, q1 * q1);
        #pragma unroll
        for (int o = 16; o > 0; o >>= 1) qsq += __shfl_xor_sync(0xffffffffu, qsq, o);

        float u0 = 0.f, u1 = 0.f;
        #pragma unroll
        for (int d = 0; d < 32; d++) {
            float qd = __shfl_sync(0xffffffffu, q0, d);
            u0 = fmaf(qd, ws[d * 64 + lane], u0);
            u1 = fmaf(qd, ws[d * 64 + lane + 32], u1);
        }
        #pragma unroll
        for (int d = 0; d < 32; d++) {
            float qd = __shfl_sync(0xffffffffu, q1, d);
            u0 = fmaf(qd, ws[(d + 32) * 64 + lane], u0);
            u1 = fmaf(qd, ws[(d + 32) * 64 + lane + 32], u1);
        }
        const float c = -0.5f * qsq;
        float p0 = __expf(u0 + c) * RSQRT_M;   // qp[lane]
        float p1 = __expf(u1 + c) * RSQRT_M;   // qp[lane+32]

        float a0 = 0.f, a1 = 0.f, den = 0.f;
        #pragma unroll
        for (int mi = 0; mi < 32; mi++) {
            float pm = __shfl_sync(0xffffffffu, p0, mi);
            a0  = fmaf(pm, b1s[mi * 66 + lane], a0);
            a1  = fmaf(pm, b1s[mi * 66 + lane + 32], a1);
            den = fmaf(pm, b1s[mi * 66 + 64], den);
        }
        #pragma unroll
        for (int mi = 0; mi < 32; mi++) {
            float pm = __shfl_sync(0xffffffffu, p1, mi);
            a0  = fmaf(pm, b1s[(mi + 32) * 66 + lane], a0);
            a1  = fmaf(pm, b1s[(mi + 32) * 66 + lane + 32], a1);
            den = fmaf(pm, b1s[(mi + 32) * 66 + 64], den);
        }
        float inv = 1.0f / den;
        Oc[r * Dc + lane]      = a0 * inv;
        Oc[r * Dc + lane + 32] = a1 * inv;
    }
}

// ---------------------------------------------------------------------------
extern "C" void kernel_launch(void* const* d_in, const int* in_sizes, int n_in,
                              void* d_out, int out_size) {
    const float* Q = (const float*)d_in[0];
    const float* K = (const float*)d_in[1];
    const float* V = (const float*)d_in[2];
    const float* W = (const float*)d_in[3];
    float* O = (float*)d_out;

    const int smem1 = (64 * 64 + CHUNK * 64 + CHUNK * EP) * sizeof(float);  // ~84 KB
    const int smem2 = (64 * 64 + 64 * 66) * sizeof(float);                  // ~33 KB

    // Idempotent; ignore errors (attribute persists from the pre-capture call).
    cudaFuncSetAttribute(phase1, cudaFuncAttributeMaxDynamicSharedMemorySize, smem1);
    cudaFuncSetAttribute(phase2, cudaFuncAttributeMaxDynamicSharedMemorySize, smem2);

    zero_buf1<<<(BH * Mc * Ec + 255) / 256, 256>>>();
    phase1<<<dim3(NCHUNK, BH), 256, smem1>>>(K, V, W);
    phase2<<<dim3(NCHUNK, BH), 256, smem2>>>(Q, W, O);
}

// round 2
// speedup vs baseline: 2.6903x; 2.6903x over previous
#include <cuda_runtime.h>
#include <cuda_bf16.h>

// Performer (FAVOR+) linear attention — register-tiled fp32 SIMT.
// B=4 H=16 S=4096 D=64 M=64. Output fp32 (B,H,S,D).

#define Sc 4096
#define BH 64
#define CHUNK 128
#define NCHUNK 32
#define XT_P 132      // xT row pad (floats): 528B rows, 16B-aligned LDS.128, conflict-free
#define B1_P 68       // g_buf1 row pad: cols 0..63 num, 64 den, 65..67 zero pad

// buf1 = kp^T @ [V,1] per (b,h): [BH][64][B1_P]
__device__ float g_buf1[BH * 64 * B1_P];

__global__ void zero_buf1() {
    int i = blockIdx.x * blockDim.x + threadIdx.x;
    if (i < BH * 64 * B1_P) g_buf1[i] = 0.0f;
}

// ---------------------------------------------------------------------------
// Phase 1: kp = exp(K·Ω − ½‖K‖²)/8 ; g_buf1 += kp^T · [V,1]
// grid (NCHUNK, BH), 512 threads.
// smem: ws[64][64] | xT[64][XT_P] | kps[128][64] (aliased K-staging) | cs[128][64] | ksq[128]
// ---------------------------------------------------------------------------
__global__ __launch_bounds__(512) void phase1(const float* __restrict__ K,
                                              const float* __restrict__ V,
                                              const float* __restrict__ W) {
    extern __shared__ float sm[];
    float* ws  = sm;                 // 4096
    float* xT  = ws + 4096;          // 64*XT_P = 8448
    float* kps = xT + 64 * XT_P;     // 8192 (aliased as xs staging)
    float* cs  = kps + 8192;         // 8192
    float* ksq = cs + 8192;          // 128
    float* xs  = kps;

    const int tid = threadIdx.x;
    const int bh = blockIdx.y;
    const size_t base = ((size_t)bh * Sc + (size_t)blockIdx.x * CHUNK) * 64;

    // ---- global loads (coalesced float4) ----
    {
        const float4* W4 = (const float4*)W;
        const float4* K4 = (const float4*)(K + base);
        const float4* V4 = (const float4*)(V + base);
        #pragma unroll
        for (int i = 0; i < 2; i++) ((float4*)ws)[tid + 512 * i] = W4[tid + 512 * i];
        #pragma unroll
        for (int i = 0; i < 4; i++) {
            int idx = tid + 512 * i;
            ((float4*)xs)[idx] = K4[idx];
            ((float4*)cs)[idx] = V4[idx];
        }
    }
    __syncthreads();

    // ---- transpose xs[128][64] -> xT[64][XT_P] ----
    {
        const int k = tid & 63;
        const int rg0 = tid >> 6;
        #pragma unroll
        for (int i = 0; i < 4; i++) {
            int r0 = 4 * (rg0 + 8 * i);
            float4 t;
            t.x = xs[(r0 + 0) * 64 + k];
            t.y = xs[(r0 + 1) * 64 + k];
            t.z = xs[(r0 + 2) * 64 + k];
            t.w = xs[(r0 + 3) * 64 + k];
            *(float4*)&xT[k * XT_P + r0] = t;
        }
    }
    __syncthreads();

    // ---- ksq[r] = -0.5 * sum_k x[r][k]^2 ----
    if (tid < 128) {
        float s0 = 0.f, s1 = 0.f;
        #pragma unroll
        for (int k = 0; k < 64; k += 2) {
            float x0 = xT[k * XT_P + tid];
            float x1 = xT[(k + 1) * XT_P + tid];
            s0 = fmaf(x0, x0, s0);
            s1 = fmaf(x1, x1, s1);
        }
        ksq[tid] = -0.5f * (s0 + s1);
    }
    __syncthreads();

    // ---- stage A: U[r][m] = sum_k x[r][k] w[k][m], 4x4 register tile ----
    const int tc = tid & 15;   // m-group
    const int tr = tid >> 4;   // r-group
    float acc[4][4] = {};
    {
        const float* xTp = xT + 4 * tr;
        const float* wp  = ws + 4 * tc;
        #pragma unroll
        for (int k = 0; k < 64; k++) {
            float4 a = *(const float4*)(xTp + k * XT_P);
            float4 b = *(const float4*)(wp + k * 64);
            acc[0][0] = fmaf(a.x, b.x, acc[0][0]); acc[0][1] = fmaf(a.x, b.y, acc[0][1]);
            acc[0][2] = fmaf(a.x, b.z, acc[0][2]); acc[0][3] = fmaf(a.x, b.w, acc[0][3]);
            acc[1][0] = fmaf(a.y, b.x, acc[1][0]); acc[1][1] = fmaf(a.y, b.y, acc[1][1]);
            acc[1][2] = fmaf(a.y, b.z, acc[1][2]); acc[1][3] = fmaf(a.y, b.w, acc[1][3]);
            acc[2][0] = fmaf(a.z, b.x, acc[2][0]); acc[2][1] = fmaf(a.z, b.y, acc[2][1]);
            acc[2][2] = fmaf(a.z, b.z, acc[2][2]); acc[2][3] = fmaf(a.z, b.w, acc[2][3]);
            acc[3][0] = fmaf(a.w, b.x, acc[3][0]); acc[3][1] = fmaf(a.w, b.y, acc[3][1]);
            acc[3][2] = fmaf(a.w, b.z, acc[3][2]); acc[3][3] = fmaf(a.w, b.w, acc[3][3]);
        }
    }

    // ---- stage B: kp = exp(U + ksq)*0.125, write kps[r][m] (xs is dead) ----
    {
        float kq[4];
        #pragma unroll
        for (int i = 0; i < 4; i++) kq[i] = ksq[4 * tr + i];
        #pragma unroll
        for (int i = 0; i < 4; i++) {
            float4 t;
            t.x = __expf(acc[i][0] + kq[i]) * 0.125f;
            t.y = __expf(acc[i][1] + kq[i]) * 0.125f;
            t.z = __expf(acc[i][2] + kq[i]) * 0.125f;
            t.w = __expf(acc[i][3] + kq[i]) * 0.125f;
            *(float4*)&kps[(4 * tr + i) * 64 + 4 * tc] = t;
        }
    }
    __syncthreads();

    // ---- stage C: buf1[m][e] += sum_r kp[r][m] * C[r][e], 4x2 tile ----
    {
        const int te = tid & 31;   // e-group (2 wide)
        const int tm = tid >> 5;   // m-group (4 wide)
        float bacc[4][2] = {};
        const float* kp_p = kps + 4 * tm;
        const float* cp   = cs + 2 * te;
        #pragma unroll 4
        for (int r = 0; r < 128; r++) {
            float4 a = *(const float4*)(kp_p + r * 64);
            float2 b = *(const float2*)(cp + r * 64);
            bacc[0][0] = fmaf(a.x, b.x, bacc[0][0]); bacc[0][1] = fmaf(a.x, b.y, bacc[0][1]);
            bacc[1][0] = fmaf(a.y, b.x, bacc[1][0]); bacc[1][1] = fmaf(a.y, b.y, bacc[1][1]);
            bacc[2][0] = fmaf(a.z, b.x, bacc[2][0]); bacc[2][1] = fmaf(a.z, b.y, bacc[2][1]);
            bacc[3][0] = fmaf(a.w, b.x, bacc[3][0]); bacc[3][1] = fmaf(a.w, b.y, bacc[3][1]);
        }
        float* b1 = g_buf1 + ((size_t)bh * 64 + 4 * tm) * B1_P + 2 * te;
        #pragma unroll
        for (int i = 0; i < 4; i++) {
            atomicAdd(&b1[i * B1_P],     bacc[i][0]);
            atomicAdd(&b1[i * B1_P + 1], bacc[i][1]);
        }
    }
    // ---- denominator column: buf1[m][64] += sum_r kp[r][m] ----
    if (tid < 64) {
        float s = 0.f;
        #pragma unroll 8
        for (int r = 0; r < 128; r++) s += kps[r * 64 + tid];
        atomicAdd(&g_buf1[((size_t)bh * 64 + tid) * B1_P + 64], s);
    }
}

// ---------------------------------------------------------------------------
// Phase 2: qp = exp(Q·Ω − ½‖Q‖²)/8 ; out = (qp·buf1[:,:64]) / (qp·buf1[:,64])
// grid (NCHUNK, BH), 512 threads.
// smem: ws | xT | qps[128][64] (aliased Q-staging) | b1s[64][B1_P] | ksq[128]
// ---------------------------------------------------------------------------
__global__ __launch_bounds__(512) void phase2(const float* __restrict__ Q,
                                              const float* __restrict__ W,
                                              float* __restrict__ O) {
    extern __shared__ float sm[];
    float* ws  = sm;                 // 4096
    float* xT  = ws + 4096;          // 8448
    float* qps = xT + 64 * XT_P;     // 8192 (aliased staging)
    float* b1s = qps + 8192;         // 64*B1_P = 4352
    float* ksq = b1s + 64 * B1_P;    // 128
    float* xs  = qps;

    const int tid = threadIdx.x;
    const int bh = blockIdx.y;
    const size_t base = ((size_t)bh * Sc + (size_t)blockIdx.x * CHUNK) * 64;

    // ---- global loads ----
    {
        const float4* W4 = (const float4*)W;
        const float4* Q4 = (const float4*)(Q + base);
        const float4* B4 = (const float4*)(g_buf1 + (size_t)bh * 64 * B1_P);
        #pragma unroll
        for (int i = 0; i < 2; i++) ((float4*)ws)[tid + 512 * i] = W4[tid + 512 * i];
        #pragma unroll
        for (int i = 0; i < 4; i++) {
            int idx = tid + 512 * i;
            ((float4*)xs)[idx] = Q4[idx];
        }
        #pragma unroll
        for (int i = 0; i < 3; i++) {
            int idx = tid + 512 * i;
            if (idx < 64 * B1_P / 4) ((float4*)b1s)[idx] = B4[idx];
        }
    }
    __syncthreads();

    // ---- transpose xs -> xT ----
    {
        const int k = tid & 63;
        const int rg0 = tid >> 6;
        #pragma unroll
        for (int i = 0; i < 4; i++) {
            int r0 = 4 * (rg0 + 8 * i);
            float4 t;
            t.x = xs[(r0 + 0) * 64 + k];
            t.y = xs[(r0 + 1) * 64 + k];
            t.z = xs[(r0 + 2) * 64 + k];
            t.w = xs[(r0 + 3) * 64 + k];
            *(float4*)&xT[k * XT_P + r0] = t;
        }
    }
    __syncthreads();

    if (tid < 128) {
        float s0 = 0.f, s1 = 0.f;
        #pragma unroll
        for (int k = 0; k < 64; k += 2) {
            float x0 = xT[k * XT_P + tid];
            float x1 = xT[(k + 1) * XT_P + tid];
            s0 = fmaf(x0, x0, s0);
            s1 = fmaf(x1, x1, s1);
        }
        ksq[tid] = -0.5f * (s0 + s1);
    }
    __syncthreads();

    // ---- stage A: U = X·Ω ----
    const int tc = tid & 15;
    const int tr = tid >> 4;
    float acc[4][4] = {};
    {
        const float* xTp = xT + 4 * tr;
        const float* wp  = ws + 4 * tc;
        #pragma unroll
        for (int k = 0; k < 64; k++) {
            float4 a = *(const float4*)(xTp + k * XT_P);
            float4 b = *(const float4*)(wp + k * 64);
            acc[0][0] = fmaf(a.x, b.x, acc[0][0]); acc[0][1] = fmaf(a.x, b.y, acc[0][1]);
            acc[0][2] = fmaf(a.x, b.z, acc[0][2]); acc[0][3] = fmaf(a.x, b.w, acc[0][3]);
            acc[1][0] = fmaf(a.y, b.x, acc[1][0]); acc[1][1] = fmaf(a.y, b.y, acc[1][1]);
            acc[1][2] = fmaf(a.y, b.z, acc[1][2]); acc[1][3] = fmaf(a.y, b.w, acc[1][3]);
            acc[2][0] = fmaf(a.z, b.x, acc[2][0]); acc[2][1] = fmaf(a.z, b.y, acc[2][1]);
            acc[2][2] = fmaf(a.z, b.z, acc[2][2]); acc[2][3] = fmaf(a.z, b.w, acc[2][3]);
            acc[3][0] = fmaf(a.w, b.x, acc[3][0]); acc[3][1] = fmaf(a.w, b.y, acc[3][1]);
            acc[3][2] = fmaf(a.w, b.z, acc[3][2]); acc[3][3] = fmaf(a.w, b.w, acc[3][3]);
        }
    }
    // ---- stage B: qp -> qps[r][m] ----
    {
        float kq[4];
        #pragma unroll
        for (int i = 0; i < 4; i++) kq[i] = ksq[4 * tr + i];
        #pragma unroll
        for (int i = 0; i < 4; i++) {
            float4 t;
            t.x = __expf(acc[i][0] + kq[i]) * 0.125f;
            t.y = __expf(acc[i][1] + kq[i]) * 0.125f;
            t.z = __expf(acc[i][2] + kq[i]) * 0.125f;
            t.w = __expf(acc[i][3] + kq[i]) * 0.125f;
            *(float4*)&qps[(4 * tr + i) * 64 + 4 * tc] = t;
        }
    }
    __syncthreads();

    // ---- stage C': out[r][d] = sum_m qp[r][m]·b1[m][d] / (sum_m qp[r][m]·b1[m][64]) ----
    {
        float oacc[4][4] = {};
        float dn[4] = {};
        const float* qp_p = qps + (4 * tr) * 64;
        const float* bp   = b1s + 4 * tc;
        #pragma unroll 2
        for (int m = 0; m < 64; m += 4) {
            float a[4][4];
            #pragma unroll
            for (int i = 0; i < 4; i++)
                *(float4*)a[i] = *(const float4*)(qp_p + i * 64 + m);
            #pragma unroll
            for (int mm = 0; mm < 4; mm++) {
                float4 b = *(const float4*)(bp + (m + mm) * B1_P);
                float dB = b1s[(m + mm) * B1_P + 64];
                #pragma unroll
                for (int i = 0; i < 4; i++) {
                    float av = a[i][mm];
                    oacc[i][0] = fmaf(av, b.x, oacc[i][0]);
                    oacc[i][1] = fmaf(av, b.y, oacc[i][1]);
                    oacc[i][2] = fmaf(av, b.z, oacc[i][2]);
                    oacc[i][3] = fmaf(av, b.w, oacc[i][3]);
                    dn[i]      = fmaf(av, dB,  dn[i]);
                }
            }
        }
        float* Op = O + base + (size_t)(4 * tr) * 64 + 4 * tc;
        #pragma unroll
        for (int i = 0; i < 4; i++) {
            float inv = 1.0f / dn[i];
            float4 t;
            t.x = oacc[i][0] * inv; t.y = oacc[i][1] * inv;
            t.z = oacc[i][2] * inv; t.w = oacc[i][3] * inv;
            *(float4*)(Op + i * 64) = t;
        }
    }
}

// ---------------------------------------------------------------------------
extern "C" void kernel_launch(void* const* d_in, const int* in_sizes, int n_in,
                              void* d_out, int out_size) {
    const float* Q = (const float*)d_in[0];
    const float* K = (const float*)d_in[1];
    const float* V = (const float*)d_in[2];
    const float* W = (const float*)d_in[3];
    float* O = (float*)d_out;

    const int smem1 = (4096 + 64 * XT_P + 8192 + 8192 + 128) * sizeof(float); // 116224 B
    const int smem2 = (4096 + 64 * XT_P + 8192 + 64 * B1_P + 128) * sizeof(float); // 100864 B

    cudaFuncSetAttribute(phase1, cudaFuncAttributeMaxDynamicSharedMemorySize, smem1);
    cudaFuncSetAttribute(phase2, cudaFuncAttributeMaxDynamicSharedMemorySize, smem2);

    const int nzero = BH * 64 * B1_P;
    zero_buf1<<<(nzero + 255) / 256, 256>>>();
    phase1<<<dim3(NCHUNK, BH), 512, smem1>>>(K, V, W);
    phase2<<<dim3(NCHUNK, BH), 512, smem2>>>(Q, W, O);
}